// round 2
// baseline (speedup 1.0000x reference)
#include <cuda_runtime.h>
#include <math.h>

// Problem constants
#define BB 16
#define LL 64
#define DD 256
#define NR 8
#define MROWS (BB * LL)     // 1024
#define KTOT (LL * NR)      // 512

// ---------------- device scratch (allocation-free rule: static __device__) ----
__device__ float g_h[MROWS * DD];            // carry h (1 MB), read by k_proj, overwritten by k_step
__device__ float g_p[MROWS * NR * DD];       // p[b*512 + i*8 + r][d]  (8 MB)
__device__ float g_ssp[3][MROWS * DD];       // 0=shift, 1=scale, 2=proj_x (3 MB)
__device__ int   g_len[BB];

// ---------------- init: zero carry + compute lengths -------------------------
__global__ __launch_bounds__(256) void k_init(const int* __restrict__ tokens) {
    int idx = blockIdx.x * 256 + threadIdx.x;
    g_h[idx] = 0.0f;
    if (blockIdx.x == 0 && threadIdx.x < BB) {
        int b = threadIdx.x, c = 0;
        for (int l = 0; l < LL; l++) c += (tokens[l * BB + b] != 0);
        g_len[b] = c;
    }
}

// ---------------- in_proj (once): [emb gather] @ W_in + b_in -> shift/scale/proj_x
// grid (32, 3): x = 32-row tile, y = output slot (col block of 256 in the 768-wide result)
__global__ __launch_bounds__(256) void k_inproj(const int* __restrict__ tokens,
                                                const float* __restrict__ emb,
                                                const float* __restrict__ W_in,
                                                const float* __restrict__ b_in) {
    __shared__ float sX[32 * 32];
    __shared__ float sW[32 * 256];
    const int m0 = blockIdx.x * 32;
    const int y  = blockIdx.y;
    const int tid = threadIdx.x, lane = tid & 31, wg = tid >> 5;

    float acc[4][8];
#pragma unroll
    for (int v = 0; v < 4; v++)
#pragma unroll
        for (int u = 0; u < 8; u++) acc[v][u] = 0.0f;

    for (int k0 = 0; k0 < DD; k0 += 32) {
        for (int idx = tid; idx < 32 * 32; idx += 256) {
            int m = idx >> 5, k = idx & 31;
            int row = m0 + m, b = row >> 6, l = row & 63;
            int t = tokens[l * BB + b];
            sX[idx] = emb[t * DD + k0 + k];
        }
        for (int idx = tid; idx < 32 * 256; idx += 256) {
            int k = idx >> 8, n = idx & 255;
            sW[idx] = W_in[(k0 + k) * 768 + y * 256 + n];
        }
        __syncthreads();
#pragma unroll
        for (int k = 0; k < 32; k++) {
            float a[4], w[8];
#pragma unroll
            for (int v = 0; v < 4; v++) a[v] = sX[(wg * 4 + v) * 32 + k];
#pragma unroll
            for (int u = 0; u < 8; u++) w[u] = sW[k * 256 + lane + 32 * u];
#pragma unroll
            for (int v = 0; v < 4; v++)
#pragma unroll
                for (int u = 0; u < 8; u++) acc[v][u] += a[v] * w[u];
        }
        __syncthreads();
    }
#pragma unroll
    for (int v = 0; v < 4; v++) {
        int row = m0 + wg * 4 + v;
#pragma unroll
        for (int u = 0; u < 8; u++) {
            int col = lane + 32 * u;
            g_ssp[y][row * DD + col] = acc[v][u] + b_in[y * 256 + col];
        }
    }
}

// ---------------- per step kernel A: p = LN(h @ Wp + bp) ----------------------
// grid (32, 8): x = 32-row tile of h, y = relation r (col block of 256 in the 2048-wide result)
__global__ __launch_bounds__(256) void k_proj(const float* __restrict__ Wp,
                                              const float* __restrict__ bp) {
    __shared__ float sX[32 * 32];
    __shared__ float sW[32 * 256];   // reused as the output tile for LN
    const int m0 = blockIdx.x * 32;
    const int r  = blockIdx.y;
    const int tid = threadIdx.x, lane = tid & 31, wg = tid >> 5;

    float acc[4][8];
#pragma unroll
    for (int v = 0; v < 4; v++)
#pragma unroll
        for (int u = 0; u < 8; u++) acc[v][u] = 0.0f;

    for (int k0 = 0; k0 < DD; k0 += 32) {
        for (int idx = tid; idx < 32 * 32; idx += 256) {
            int m = idx >> 5, k = idx & 31;
            sX[idx] = g_h[(m0 + m) * DD + k0 + k];
        }
        for (int idx = tid; idx < 32 * 256; idx += 256) {
            int k = idx >> 8, n = idx & 255;
            sW[idx] = Wp[(k0 + k) * 2048 + r * 256 + n];
        }
        __syncthreads();
#pragma unroll
        for (int k = 0; k < 32; k++) {
            float a[4], w[8];
#pragma unroll
            for (int v = 0; v < 4; v++) a[v] = sX[(wg * 4 + v) * 32 + k];
#pragma unroll
            for (int u = 0; u < 8; u++) w[u] = sW[k * 256 + lane + 32 * u];
#pragma unroll
            for (int v = 0; v < 4; v++)
#pragma unroll
                for (int u = 0; u < 8; u++) acc[v][u] += a[v] * w[u];
        }
        __syncthreads();
    }
    // stage tile (with bias) into sW, then per-row LayerNorm (warp wg -> rows 4wg..4wg+3)
#pragma unroll
    for (int v = 0; v < 4; v++)
#pragma unroll
        for (int u = 0; u < 8; u++)
            sW[(wg * 4 + v) * 256 + lane + 32 * u] = acc[v][u] + bp[r * 256 + lane + 32 * u];
    __syncthreads();

#pragma unroll
    for (int v = 0; v < 4; v++) {
        int rr = wg * 4 + v;
        float x[8], s = 0.0f, s2 = 0.0f;
#pragma unroll
        for (int u = 0; u < 8; u++) {
            x[u] = sW[rr * 256 + lane + 32 * u];
            s += x[u];
            s2 += x[u] * x[u];
        }
#pragma unroll
        for (int o = 16; o > 0; o >>= 1) {
            s  += __shfl_xor_sync(0xffffffffu, s,  o);
            s2 += __shfl_xor_sync(0xffffffffu, s2, o);
        }
        float mean = s * (1.0f / 256.0f);
        float var  = s2 * (1.0f / 256.0f) - mean * mean;
        float inv  = rsqrtf(var + 1e-5f);
        int row = m0 + rr;
#pragma unroll
        for (int u = 0; u < 8; u++)
            g_p[(row * NR + r) * DD + lane + 32 * u] = (x[u] - mean) * inv;
    }
}

// ---------------- per step kernel B: fused einsum + shrink + LN + gate + out GEMM + tanh + mask
// grid (8, 16): x = 8-row j chunk, y = batch b. warp wg owns local row jj = wg.
__global__ __launch_bounds__(256) void k_step(const float* __restrict__ A,
                                              const float* __restrict__ Wout,
                                              const float* __restrict__ bout,
                                              int istep) {
    __shared__ float sA[8 * 32];
    __shared__ float sP[32 * 256];   // reused as h-row staging after the K loop
    const int b = blockIdx.y, jc = blockIdx.x;
    const int tid = threadIdx.x, lane = tid & 31, wg = tid >> 5;
    const int jj = wg;
    const int j  = jc * 8 + jj;
    const int row = b * LL + j;

    float acc[8];
#pragma unroll
    for (int u = 0; u < 8; u++) acc[u] = 0.0f;

    for (int k0 = 0; k0 < KTOT; k0 += 32) {
        {   // 8x32 = 256 elems, one per thread
            int jl = tid >> 5, kk = tid & 31;
            int kg = k0 + kk, i = kg >> 3, hh = kg & 7;
            sA[tid] = A[((b * LL + i) * LL + (jc * 8 + jl)) * NR + hh];
        }
        for (int idx = tid; idx < 32 * 256; idx += 256) {
            int kk = idx >> 8, d = idx & 255;
            sP[idx] = g_p[(b * KTOT + k0 + kk) * DD + d];
        }
        __syncthreads();
#pragma unroll
        for (int k = 0; k < 32; k++) {
            float a = sA[jj * 32 + k];
#pragma unroll
            for (int u = 0; u < 8; u++) acc[u] += a * sP[k * 256 + lane + 32 * u];
        }
        __syncthreads();
    }

    // shrink + proj_x (in registers), then LN across the warp via shfl
    float t[8], s = 0.0f, s2 = 0.0f;
#pragma unroll
    for (int u = 0; u < 8; u++) {
        int d = lane + 32 * u;
        float ls = acc[u];
        t[u] = g_ssp[2][row * DD + d] + ls - tanhf(ls);
        s += t[u];
        s2 += t[u] * t[u];
    }
#pragma unroll
    for (int o = 16; o > 0; o >>= 1) {
        s  += __shfl_xor_sync(0xffffffffu, s,  o);
        s2 += __shfl_xor_sync(0xffffffffu, s2, o);
    }
    float mean = s * (1.0f / 256.0f);
    float var  = s2 * (1.0f / 256.0f) - mean * mean;
    float inv  = rsqrtf(var + 1e-5f);

    // gated update h = relu(shift*LN + scale); stage h row in smem (each warp owns its row)
    float* sHt = sP;
#pragma unroll
    for (int u = 0; u < 8; u++) {
        int d = lane + 32 * u;
        float ln = (t[u] - mean) * inv;
        float hv = g_ssp[0][row * DD + d] * ln + g_ssp[1][row * DD + d];
        sHt[jj * 256 + d] = fmaxf(hv, 0.0f);
    }
    __syncwarp();

    // output GEMM: y = tanh(h @ Wout + bout), masked
    float acc2[8];
#pragma unroll
    for (int u = 0; u < 8; u++) acc2[u] = 0.0f;
#pragma unroll 4
    for (int k = 0; k < 256; k++) {
        float hv = sHt[jj * 256 + k];
#pragma unroll
        for (int u = 0; u < 8; u++) acc2[u] += hv * Wout[k * 256 + lane + 32 * u];
    }
    bool maskz = (istep > g_len[b]);
#pragma unroll
    for (int u = 0; u < 8; u++) {
        int d = lane + 32 * u;
        float yv = tanhf(acc2[u] + bout[d]);
        g_h[row * DD + d] = maskz ? 0.0f : yv;
    }
}

// ---------------- final: out[b,d] = sum_i h[b,i,d] * root[b,i] ----------------
__global__ __launch_bounds__(256) void k_final(const float* __restrict__ root,
                                               float* __restrict__ out) {
    int b = blockIdx.x, d = threadIdx.x;
    float s = 0.0f;
    for (int i = 0; i < LL; i++)
        s += g_h[(b * LL + i) * DD + d] * root[b * LL + i];
    out[b * DD + d] = s;
}

extern "C" void kernel_launch(void* const* d_in, const int* in_sizes, int n_in,
                              void* d_out, int out_size) {
    const int*   tokens = (const int*)  d_in[0];
    const float* A      = (const float*)d_in[1];
    const float* root   = (const float*)d_in[2];
    const float* emb    = (const float*)d_in[3];
    const float* Wp     = (const float*)d_in[4];
    const float* bp     = (const float*)d_in[5];
    const float* W_in   = (const float*)d_in[6];
    const float* b_in   = (const float*)d_in[7];
    const float* Wout   = (const float*)d_in[8];
    const float* bout   = (const float*)d_in[9];
    float* out = (float*)d_out;

    k_init<<<MROWS, 256>>>(tokens);
    k_inproj<<<dim3(32, 3), 256>>>(tokens, emb, W_in, b_in);
    for (int s = 0; s < LL; s++) {
        int i = LL - s;   // i = 64 .. 1
        k_proj<<<dim3(32, 8), 256>>>(Wp, bp);
        k_step<<<dim3(8, 16), 256>>>(A, Wout, bout, i);
    }
    k_final<<<BB, 256>>>(root, out);
}

// round 4
// speedup vs baseline: 1.3198x; 1.3198x over previous
#include <cuda_runtime.h>
#include <math.h>

#define NB 128
#define NT 512

typedef unsigned long long u64;

// ---------------- device scratch ----------------
__device__ float g_h[1024 * 256];            // carry h  (1 MB)
__device__ float g_p[1024 * 8 * 256];        // p[b*512 + i*8 + r][d] (8 MB)
__device__ float g_ssp[3][1024 * 256];       // shift / scale / proj_x
__device__ int   g_len[16];
__device__ unsigned g_cnt;                   // grid barrier counter

// ---------------- f32x2 helpers ----------------
__device__ __forceinline__ void fma2(u64& d, u64 a, u64 b) {
    asm("fma.rn.f32x2 %0, %1, %2, %0;" : "+l"(d) : "l"(a), "l"(b));
}
__device__ __forceinline__ float psum(u64 v) {
    float a, b;
    asm("mov.b64 {%0,%1}, %2;" : "=f"(a), "=f"(b) : "l"(v));
    return a + b;
}

// ---------------- grid-wide barrier (all 128 CTAs resident: 1 CTA/SM) -------
__device__ __forceinline__ void gsync() {
    __syncthreads();
    if (threadIdx.x == 0) {
        __threadfence();                                   // release all prior writes
        unsigned ticket = atomicAdd(&g_cnt, 1u);
        unsigned target = (ticket | (NB - 1)) + 1;         // next multiple of NB
        unsigned v;
        do {
            asm volatile("ld.acquire.gpu.u32 %0, [%1];" : "=r"(v) : "l"(&g_cnt) : "memory");
        } while (v < target);
    }
    __syncthreads();
}

__global__ void k_reset() { g_cnt = 0u; }

// smem carve-out (floats):
//  GEMM phases: sX[1024] @0, sWt[256*34=8704] @1024, sRed @9728 (<=256)
//  phase B:     sAa[256] @0, sPt[8704] @1024, sH[2048] @9728, sRed[128] @11776
#define SM_TOTAL 11904

__global__ __launch_bounds__(NT, 1) void k_persist(
    const int*   __restrict__ tokens, const float* __restrict__ A,
    const float* __restrict__ root,   const float* __restrict__ emb,
    const float* __restrict__ Wp,     const float* __restrict__ bp,
    const float* __restrict__ W_in,   const float* __restrict__ b_in,
    const float* __restrict__ Wout,   const float* __restrict__ bout,
    float* __restrict__ out)
{
    __shared__ __align__(16) float sm[SM_TOTAL];
    const int tid  = threadIdx.x, lane = tid & 31, w = tid >> 5;
    const int bid  = blockIdx.x;

    // =================== prologue ===================
    for (int i = bid * NT + tid; i < 1024 * 256; i += NB * NT) g_h[i] = 0.0f;
    if (bid == 0 && tid < 16) {
        int c = 0;
        for (int l = 0; l < 64; l++) c += (tokens[l * 16 + tid] != 0);
        g_len[tid] = c;
    }
    // in_proj: 96 tiles (y<3 slots x 32 m-tiles), one per CTA
    if (bid < 96) {
        const int y = bid >> 5, m0 = (bid & 31) * 32;
        const int wm = w >> 2, wn = w & 3;                 // 4x4 warp grid
        float* sX = sm; float* sWt = sm + 1024;
        u64 acc[8][2];
#pragma unroll
        for (int v = 0; v < 8; v++) { acc[v][0] = 0ull; acc[v][1] = 0ull; }
        for (int k0 = 0; k0 < 256; k0 += 32) {
            for (int i = tid; i < 1024; i += NT) {
                int m = i >> 5, k = i & 31, row = m0 + m;
                int tok = tokens[(row & 63) * 16 + (row >> 6)];
                sX[i] = emb[tok * 256 + k0 + k];
            }
            for (int i = tid; i < 8192; i += NT) {
                int k = i >> 8, n = i & 255;
                sWt[n * 34 + k] = W_in[(k0 + k) * 768 + y * 256 + n];
            }
            __syncthreads();
#pragma unroll
            for (int kk = 0; kk < 16; kk++) {
                u64 a[8], wv[2];
#pragma unroll
                for (int v = 0; v < 8; v++)
                    a[v] = *(const u64*)&sX[(8 * wm + v) * 32 + 2 * kk];
#pragma unroll
                for (int u = 0; u < 2; u++)
                    wv[u] = *(const u64*)&sWt[(64 * wn + lane + 32 * u) * 34 + 2 * kk];
#pragma unroll
                for (int v = 0; v < 8; v++)
#pragma unroll
                    for (int u = 0; u < 2; u++) fma2(acc[v][u], a[v], wv[u]);
            }
            __syncthreads();
        }
#pragma unroll
        for (int v = 0; v < 8; v++) {
            int row = m0 + 8 * wm + v;
#pragma unroll
            for (int u = 0; u < 2; u++) {
                int c = 64 * wn + lane + 32 * u;
                g_ssp[y][row * 256 + c] = psum(acc[v][u]) + b_in[y * 256 + c];
            }
        }
    }
    gsync();

    // =================== 64 recurrent steps ===================
    for (int s = 0; s < 64; s++) {
        // ---------- phase A: p = LN(h @ Wp + bp), 256 tiles, 2 per CTA ----------
        for (int t = bid; t < 256; t += NB) {
            const int m0 = (t >> 3) * 32;
            const int r  = t & 7;
            const int wm = w >> 2, wn = w & 3;
            float* sX = sm; float* sWt = sm + 1024; float* sRed = sm + 9728;
            u64 acc[8][2];
#pragma unroll
            for (int v = 0; v < 8; v++) { acc[v][0] = 0ull; acc[v][1] = 0ull; }
            for (int k0 = 0; k0 < 256; k0 += 32) {
                for (int i = tid; i < 1024; i += NT) {
                    int m = i >> 5, k = i & 31;
                    sX[i] = __ldcg(&g_h[(m0 + m) * 256 + k0 + k]);
                }
                for (int i = tid; i < 8192; i += NT) {
                    int k = i >> 8, n = i & 255;
                    sWt[n * 34 + k] = Wp[(k0 + k) * 2048 + r * 256 + n];
                }
                __syncthreads();
#pragma unroll
                for (int kk = 0; kk < 16; kk++) {
                    u64 a[8], wv[2];
#pragma unroll
                    for (int v = 0; v < 8; v++)
                        a[v] = *(const u64*)&sX[(8 * wm + v) * 32 + 2 * kk];
#pragma unroll
                    for (int u = 0; u < 2; u++)
                        wv[u] = *(const u64*)&sWt[(64 * wn + lane + 32 * u) * 34 + 2 * kk];
#pragma unroll
                    for (int v = 0; v < 8; v++)
#pragma unroll
                        for (int u = 0; u < 2; u++) fma2(acc[v][u], a[v], wv[u]);
                }
                __syncthreads();
            }
            // bias + per-row LayerNorm over 256 cols (4 wn warps cooperate)
            float x[8][2];
            float bpv[2];
#pragma unroll
            for (int u = 0; u < 2; u++) bpv[u] = bp[r * 256 + 64 * wn + lane + 32 * u];
#pragma unroll
            for (int v = 0; v < 8; v++) {
#pragma unroll
                for (int u = 0; u < 2; u++) x[v][u] = psum(acc[v][u]) + bpv[u];
                float sv  = x[v][0] + x[v][1];
                float sv2 = x[v][0] * x[v][0] + x[v][1] * x[v][1];
#pragma unroll
                for (int o = 16; o > 0; o >>= 1) {
                    sv  += __shfl_xor_sync(0xffffffffu, sv,  o);
                    sv2 += __shfl_xor_sync(0xffffffffu, sv2, o);
                }
                if (lane == 0) {
                    sRed[(8 * wm + v) * 8 + wn * 2 + 0] = sv;
                    sRed[(8 * wm + v) * 8 + wn * 2 + 1] = sv2;
                }
            }
            __syncthreads();
#pragma unroll
            for (int v = 0; v < 8; v++) {
                int row = 8 * wm + v;
                float sv = 0.0f, sv2 = 0.0f;
#pragma unroll
                for (int q = 0; q < 4; q++) {
                    sv  += sRed[row * 8 + q * 2 + 0];
                    sv2 += sRed[row * 8 + q * 2 + 1];
                }
                float mean = sv * (1.0f / 256.0f);
                float var  = sv2 * (1.0f / 256.0f) - mean * mean;
                float inv  = rsqrtf(var + 1e-5f);
#pragma unroll
                for (int u = 0; u < 2; u++) {
                    int c = 64 * wn + lane + 32 * u;
                    g_p[((m0 + row) * 8 + r) * 256 + c] = (x[v][u] - mean) * inv;
                }
            }
            __syncthreads();
        }
        gsync();

        // ---------- phase B: einsum + shrink + LN + gate + out GEMM + tanh + mask ----
        {
            const int b = bid >> 3, jc = bid & 7, j0 = jc * 8;
            const int wm = w >> 3, wn = w & 7;            // 2x8 warp grid
            const int c  = 32 * wn + lane;                // one col per thread
            float* sAa = sm; float* sPt = sm + 1024; float* sH = sm + 9728;
            float* sRed = sm + 11776;
            u64 acc[4];
#pragma unroll
            for (int v = 0; v < 4; v++) acc[v] = 0ull;
            for (int kt = 0; kt < 16; kt++) {
                if (tid < 256) {
                    int row = tid >> 5, kk = tid & 31;
                    int kg = kt * 32 + kk, i = kg >> 3, hh = kg & 7;
                    sAa[row * 32 + kk] = A[((b * 64 + i) * 64 + (j0 + row)) * 8 + hh];
                }
                for (int i = tid; i < 8192; i += NT) {
                    int kk = i >> 8, d = i & 255;
                    sPt[d * 34 + kk] = __ldcg(&g_p[(b * 512 + kt * 32 + kk) * 256 + d]);
                }
                __syncthreads();
#pragma unroll
                for (int kk = 0; kk < 16; kk++) {
                    u64 a[4];
#pragma unroll
                    for (int v = 0; v < 4; v++)
                        a[v] = *(const u64*)&sAa[(4 * wm + v) * 32 + 2 * kk];
                    u64 wv = *(const u64*)&sPt[c * 34 + 2 * kk];
#pragma unroll
                    for (int v = 0; v < 4; v++) fma2(acc[v], a[v], wv);
                }
                __syncthreads();
            }
            // shrink + proj_x, LN partials
            float tv[4];
#pragma unroll
            for (int v = 0; v < 4; v++) {
                int gr = b * 64 + j0 + 4 * wm + v;
                float lin = psum(acc[v]);
                tv[v] = g_ssp[2][gr * 256 + c] + lin - tanhf(lin);
                float sv = tv[v], sv2 = tv[v] * tv[v];
#pragma unroll
                for (int o = 16; o > 0; o >>= 1) {
                    sv  += __shfl_xor_sync(0xffffffffu, sv,  o);
                    sv2 += __shfl_xor_sync(0xffffffffu, sv2, o);
                }
                if (lane == 0) {
                    sRed[(4 * wm + v) * 16 + wn * 2 + 0] = sv;
                    sRed[(4 * wm + v) * 16 + wn * 2 + 1] = sv2;
                }
            }
            __syncthreads();
#pragma unroll
            for (int v = 0; v < 4; v++) {
                int row = 4 * wm + v, gr = b * 64 + j0 + row;
                float sv = 0.0f, sv2 = 0.0f;
#pragma unroll
                for (int q = 0; q < 8; q++) {
                    sv  += sRed[row * 16 + q * 2 + 0];
                    sv2 += sRed[row * 16 + q * 2 + 1];
                }
                float mean = sv * (1.0f / 256.0f);
                float var  = sv2 * (1.0f / 256.0f) - mean * mean;
                float inv  = rsqrtf(var + 1e-5f);
                float ln   = (tv[v] - mean) * inv;
                float hv   = g_ssp[0][gr * 256 + c] * ln + g_ssp[1][gr * 256 + c];
                sH[row * 256 + c] = fmaxf(hv, 0.0f);
            }
            __syncthreads();
            // out GEMM: y = tanh(h @ Wout + bout)
            u64 acc2[4];
#pragma unroll
            for (int v = 0; v < 4; v++) acc2[v] = 0ull;
            for (int kt = 0; kt < 8; kt++) {
                for (int i = tid; i < 8192; i += NT) {
                    int k = i >> 8, n = i & 255;
                    sPt[n * 34 + k] = Wout[(kt * 32 + k) * 256 + n];
                }
                __syncthreads();
#pragma unroll
                for (int kk = 0; kk < 16; kk++) {
                    u64 a[4];
#pragma unroll
                    for (int v = 0; v < 4; v++)
                        a[v] = *(const u64*)&sH[(4 * wm + v) * 256 + kt * 32 + 2 * kk];
                    u64 wv = *(const u64*)&sPt[c * 34 + 2 * kk];
#pragma unroll
                    for (int v = 0; v < 4; v++) fma2(acc2[v], a[v], wv);
                }
                __syncthreads();
            }
            bool mz = ((64 - s) > g_len[b]);
            float bo = bout[c];
#pragma unroll
            for (int v = 0; v < 4; v++) {
                int gr = b * 64 + j0 + 4 * wm + v;
                float yv = tanhf(psum(acc2[v]) + bo);
                g_h[gr * 256 + c] = mz ? 0.0f : yv;
            }
        }
        gsync();
    }

    // =================== final reduction ===================
    if (bid < 16 && tid < 256) {
        float sdot = 0.0f;
        for (int i = 0; i < 64; i++)
            sdot += __ldcg(&g_h[(bid * 64 + i) * 256 + tid]) * root[bid * 64 + i];
        out[bid * 256 + tid] = sdot;
    }
}

extern "C" void kernel_launch(void* const* d_in, const int* in_sizes, int n_in,
                              void* d_out, int out_size) {
    const int*   tokens = (const int*)  d_in[0];
    const float* A      = (const float*)d_in[1];
    const float* root   = (const float*)d_in[2];
    const float* emb    = (const float*)d_in[3];
    const float* Wp     = (const float*)d_in[4];
    const float* bp     = (const float*)d_in[5];
    const float* W_in   = (const float*)d_in[6];
    const float* b_in   = (const float*)d_in[7];
    const float* Wout   = (const float*)d_in[8];
    const float* bout   = (const float*)d_in[9];
    float* out = (float*)d_out;

    k_reset<<<1, 1>>>();
    k_persist<<<NB, NT>>>(tokens, A, root, emb, Wp, bp, W_in, b_in, Wout, bout, out);
}

// round 5
// speedup vs baseline: 1.3259x; 1.0046x over previous
#include <cuda_runtime.h>
#include <math.h>

#define NB 128
#define NT 512

typedef unsigned long long u64;

// ---------------- device scratch ----------------
__device__ float g_h[1024 * 256];            // carry h  (1 MB)
__device__ float g_p[1024 * 8 * 256];        // p[b*512 + i*8 + r][d] (8 MB)
__device__ float g_ssp[3][1024 * 256];       // shift / scale / proj_x
__device__ int   g_len[16];
__device__ unsigned g_cnt;                   // grid barrier counter

// ---------------- f32x2 helpers ----------------
__device__ __forceinline__ void fma2(u64& d, u64 a, u64 b) {
    asm("fma.rn.f32x2 %0, %1, %2, %0;" : "+l"(d) : "l"(a), "l"(b));
}
__device__ __forceinline__ float psum(u64 v) {
    float a, b;
    asm("mov.b64 {%0,%1}, %2;" : "=f"(a), "=f"(b) : "l"(v));
    return a + b;
}

// ---------------- grid-wide barrier (all 128 CTAs resident: 1 CTA/SM) -------
__device__ __forceinline__ void gsync() {
    __syncthreads();
    if (threadIdx.x == 0) {
        __threadfence();                                   // release all prior writes
        unsigned ticket = atomicAdd(&g_cnt, 1u);
        unsigned target = (ticket | (NB - 1)) + 1;         // next multiple of NB
        unsigned v;
        do {
            asm volatile("ld.acquire.gpu.u32 %0, [%1];" : "=r"(v) : "l"(&g_cnt) : "memory");
        } while (v < target);
    }
    __syncthreads();
}

__global__ void k_reset() { g_cnt = 0u; }

// smem carve-out (floats):
//  GEMM phases: sX[1024] @0, sWt[256*34=8704] @1024, sRed @9728 (<=256)
//  phase B:     sAa[256] @0, sPt[8704] @1024, sH[2048] @9728, sRed[128] @11776
#define SM_TOTAL 11904

__global__ __launch_bounds__(NT, 1) void k_persist(
    const int*   __restrict__ tokens, const float* __restrict__ A,
    const float* __restrict__ root,   const float* __restrict__ emb,
    const float* __restrict__ Wp,     const float* __restrict__ bp,
    const float* __restrict__ W_in,   const float* __restrict__ b_in,
    const float* __restrict__ Wout,   const float* __restrict__ bout,
    float* __restrict__ out)
{
    __shared__ __align__(16) float sm[SM_TOTAL];
    const int tid  = threadIdx.x, lane = tid & 31, w = tid >> 5;
    const int bid  = blockIdx.x;

    // =================== prologue ===================
    for (int i = bid * NT + tid; i < 1024 * 256; i += NB * NT) g_h[i] = 0.0f;
    if (bid == 0 && tid < 16) {
        int c = 0;
        for (int l = 0; l < 64; l++) c += (tokens[l * 16 + tid] != 0);
        g_len[tid] = c;
    }
    // in_proj: 96 tiles (y<3 slots x 32 m-tiles), one per CTA
    if (bid < 96) {
        const int y = bid >> 5, m0 = (bid & 31) * 32;
        const int wm = w >> 2, wn = w & 3;                 // 4x4 warp grid
        float* sX = sm; float* sWt = sm + 1024;
        u64 acc[8][2];
#pragma unroll
        for (int v = 0; v < 8; v++) { acc[v][0] = 0ull; acc[v][1] = 0ull; }
        for (int k0 = 0; k0 < 256; k0 += 32) {
            for (int i = tid; i < 1024; i += NT) {
                int m = i >> 5, k = i & 31, row = m0 + m;
                int tok = tokens[(row & 63) * 16 + (row >> 6)];
                sX[i] = emb[tok * 256 + k0 + k];
            }
            for (int i = tid; i < 8192; i += NT) {
                int k = i >> 8, n = i & 255;
                sWt[n * 34 + k] = W_in[(k0 + k) * 768 + y * 256 + n];
            }
            __syncthreads();
#pragma unroll
            for (int kk = 0; kk < 16; kk++) {
                u64 a[8], wv[2];
#pragma unroll
                for (int v = 0; v < 8; v++)
                    a[v] = *(const u64*)&sX[(8 * wm + v) * 32 + 2 * kk];
#pragma unroll
                for (int u = 0; u < 2; u++)
                    wv[u] = *(const u64*)&sWt[(64 * wn + lane + 32 * u) * 34 + 2 * kk];
#pragma unroll
                for (int v = 0; v < 8; v++)
#pragma unroll
                    for (int u = 0; u < 2; u++) fma2(acc[v][u], a[v], wv[u]);
            }
            __syncthreads();
        }
#pragma unroll
        for (int v = 0; v < 8; v++) {
            int row = m0 + 8 * wm + v;
#pragma unroll
            for (int u = 0; u < 2; u++) {
                int c = 64 * wn + lane + 32 * u;
                g_ssp[y][row * 256 + c] = psum(acc[v][u]) + b_in[y * 256 + c];
            }
        }
    }
    gsync();

    // =================== 64 recurrent steps ===================
    for (int s = 0; s < 64; s++) {
        // ---------- phase A: p = LN(h @ Wp + bp), 256 tiles, 2 per CTA ----------
        for (int t = bid; t < 256; t += NB) {
            const int m0 = (t >> 3) * 32;
            const int r  = t & 7;
            const int wm = w >> 2, wn = w & 3;
            float* sX = sm; float* sWt = sm + 1024; float* sRed = sm + 9728;
            u64 acc[8][2];
#pragma unroll
            for (int v = 0; v < 8; v++) { acc[v][0] = 0ull; acc[v][1] = 0ull; }
            for (int k0 = 0; k0 < 256; k0 += 32) {
                for (int i = tid; i < 1024; i += NT) {
                    int m = i >> 5, k = i & 31;
                    sX[i] = __ldcg(&g_h[(m0 + m) * 256 + k0 + k]);
                }
                for (int i = tid; i < 8192; i += NT) {
                    int k = i >> 8, n = i & 255;
                    sWt[n * 34 + k] = Wp[(k0 + k) * 2048 + r * 256 + n];
                }
                __syncthreads();
#pragma unroll
                for (int kk = 0; kk < 16; kk++) {
                    u64 a[8], wv[2];
#pragma unroll
                    for (int v = 0; v < 8; v++)
                        a[v] = *(const u64*)&sX[(8 * wm + v) * 32 + 2 * kk];
#pragma unroll
                    for (int u = 0; u < 2; u++)
                        wv[u] = *(const u64*)&sWt[(64 * wn + lane + 32 * u) * 34 + 2 * kk];
#pragma unroll
                    for (int v = 0; v < 8; v++)
#pragma unroll
                        for (int u = 0; u < 2; u++) fma2(acc[v][u], a[v], wv[u]);
                }
                __syncthreads();
            }
            // bias + per-row LayerNorm over 256 cols (4 wn warps cooperate)
            float x[8][2];
            float bpv[2];
#pragma unroll
            for (int u = 0; u < 2; u++) bpv[u] = bp[r * 256 + 64 * wn + lane + 32 * u];
#pragma unroll
            for (int v = 0; v < 8; v++) {
#pragma unroll
                for (int u = 0; u < 2; u++) x[v][u] = psum(acc[v][u]) + bpv[u];
                float sv  = x[v][0] + x[v][1];
                float sv2 = x[v][0] * x[v][0] + x[v][1] * x[v][1];
#pragma unroll
                for (int o = 16; o > 0; o >>= 1) {
                    sv  += __shfl_xor_sync(0xffffffffu, sv,  o);
                    sv2 += __shfl_xor_sync(0xffffffffu, sv2, o);
                }
                if (lane == 0) {
                    sRed[(8 * wm + v) * 8 + wn * 2 + 0] = sv;
                    sRed[(8 * wm + v) * 8 + wn * 2 + 1] = sv2;
                }
            }
            __syncthreads();
#pragma unroll
            for (int v = 0; v < 8; v++) {
                int row = 8 * wm + v;
                float sv = 0.0f, sv2 = 0.0f;
#pragma unroll
                for (int q = 0; q < 4; q++) {
                    sv  += sRed[row * 8 + q * 2 + 0];
                    sv2 += sRed[row * 8 + q * 2 + 1];
                }
                float mean = sv * (1.0f / 256.0f);
                float var  = sv2 * (1.0f / 256.0f) - mean * mean;
                float inv  = rsqrtf(var + 1e-5f);
#pragma unroll
                for (int u = 0; u < 2; u++) {
                    int c = 64 * wn + lane + 32 * u;
                    g_p[((m0 + row) * 8 + r) * 256 + c] = (x[v][u] - mean) * inv;
                }
            }
            __syncthreads();
        }
        gsync();

        // ---------- phase B: einsum + shrink + LN + gate + out GEMM + tanh + mask ----
        {
            const int b = bid >> 3, jc = bid & 7, j0 = jc * 8;
            const int wm = w >> 3, wn = w & 7;            // 2x8 warp grid
            const int c  = 32 * wn + lane;                // one col per thread
            float* sAa = sm; float* sPt = sm + 1024; float* sH = sm + 9728;
            float* sRed = sm + 11776;
            u64 acc[4];
#pragma unroll
            for (int v = 0; v < 4; v++) acc[v] = 0ull;
            for (int kt = 0; kt < 16; kt++) {
                if (tid < 256) {
                    int row = tid >> 5, kk = tid & 31;
                    int kg = kt * 32 + kk, i = kg >> 3, hh = kg & 7;
                    sAa[row * 32 + kk] = A[((b * 64 + i) * 64 + (j0 + row)) * 8 + hh];
                }
                for (int i = tid; i < 8192; i += NT) {
                    int kk = i >> 8, d = i & 255;
                    sPt[d * 34 + kk] = __ldcg(&g_p[(b * 512 + kt * 32 + kk) * 256 + d]);
                }
                __syncthreads();
#pragma unroll
                for (int kk = 0; kk < 16; kk++) {
                    u64 a[4];
#pragma unroll
                    for (int v = 0; v < 4; v++)
                        a[v] = *(const u64*)&sAa[(4 * wm + v) * 32 + 2 * kk];
                    u64 wv = *(const u64*)&sPt[c * 34 + 2 * kk];
#pragma unroll
                    for (int v = 0; v < 4; v++) fma2(acc[v], a[v], wv);
                }
                __syncthreads();
            }
            // shrink + proj_x, LN partials
            float tv[4];
#pragma unroll
            for (int v = 0; v < 4; v++) {
                int gr = b * 64 + j0 + 4 * wm + v;
                float lin = psum(acc[v]);
                tv[v] = g_ssp[2][gr * 256 + c] + lin - tanhf(lin);
                float sv = tv[v], sv2 = tv[v] * tv[v];
#pragma unroll
                for (int o = 16; o > 0; o >>= 1) {
                    sv  += __shfl_xor_sync(0xffffffffu, sv,  o);
                    sv2 += __shfl_xor_sync(0xffffffffu, sv2, o);
                }
                if (lane == 0) {
                    sRed[(4 * wm + v) * 16 + wn * 2 + 0] = sv;
                    sRed[(4 * wm + v) * 16 + wn * 2 + 1] = sv2;
                }
            }
            __syncthreads();
#pragma unroll
            for (int v = 0; v < 4; v++) {
                int row = 4 * wm + v, gr = b * 64 + j0 + row;
                float sv = 0.0f, sv2 = 0.0f;
#pragma unroll
                for (int q = 0; q < 8; q++) {
                    sv  += sRed[row * 16 + q * 2 + 0];
                    sv2 += sRed[row * 16 + q * 2 + 1];
                }
                float mean = sv * (1.0f / 256.0f);
                float var  = sv2 * (1.0f / 256.0f) - mean * mean;
                float inv  = rsqrtf(var + 1e-5f);
                float ln   = (tv[v] - mean) * inv;
                float hv   = g_ssp[0][gr * 256 + c] * ln + g_ssp[1][gr * 256 + c];
                sH[row * 256 + c] = fmaxf(hv, 0.0f);
            }
            __syncthreads();
            // out GEMM: y = tanh(h @ Wout + bout)
            u64 acc2[4];
#pragma unroll
            for (int v = 0; v < 4; v++) acc2[v] = 0ull;
            for (int kt = 0; kt < 8; kt++) {
                for (int i = tid; i < 8192; i += NT) {
                    int k = i >> 8, n = i & 255;
                    sPt[n * 34 + k] = Wout[(kt * 32 + k) * 256 + n];
                }
                __syncthreads();
#pragma unroll
                for (int kk = 0; kk < 16; kk++) {
                    u64 a[4];
#pragma unroll
                    for (int v = 0; v < 4; v++)
                        a[v] = *(const u64*)&sH[(4 * wm + v) * 256 + kt * 32 + 2 * kk];
                    u64 wv = *(const u64*)&sPt[c * 34 + 2 * kk];
#pragma unroll
                    for (int v = 0; v < 4; v++) fma2(acc2[v], a[v], wv);
                }
                __syncthreads();
            }
            bool mz = ((64 - s) > g_len[b]);
            float bo = bout[c];
#pragma unroll
            for (int v = 0; v < 4; v++) {
                int gr = b * 64 + j0 + 4 * wm + v;
                float yv = tanhf(psum(acc2[v]) + bo);
                g_h[gr * 256 + c] = mz ? 0.0f : yv;
            }
        }
        gsync();
    }

    // =================== final reduction ===================
    if (bid < 16 && tid < 256) {
        float sdot = 0.0f;
        for (int i = 0; i < 64; i++)
            sdot += __ldcg(&g_h[(bid * 64 + i) * 256 + tid]) * root[bid * 64 + i];
        out[bid * 256 + tid] = sdot;
    }
}

extern "C" void kernel_launch(void* const* d_in, const int* in_sizes, int n_in,
                              void* d_out, int out_size) {
    const int*   tokens = (const int*)  d_in[0];
    const float* A      = (const float*)d_in[1];
    const float* root   = (const float*)d_in[2];
    const float* emb    = (const float*)d_in[3];
    const float* Wp     = (const float*)d_in[4];
    const float* bp     = (const float*)d_in[5];
    const float* W_in   = (const float*)d_in[6];
    const float* b_in   = (const float*)d_in[7];
    const float* Wout   = (const float*)d_in[8];
    const float* bout   = (const float*)d_in[9];
    float* out = (float*)d_out;

    k_reset<<<1, 1>>>();
    k_persist<<<NB, NT>>>(tokens, A, root, emb, Wp, bp, W_in, b_in, Wout, bout, out);
}